// round 4
// baseline (speedup 1.0000x reference)
#include <cuda_runtime.h>
#include <cuda_fp16.h>
#include <math.h>
#include <stdint.h>

#define N_ROWS 500000
#define D 128
#define H 128
#define GDIM 64
#define M 256
#define TILE_R 64
#define NTILES ((N_ROWS + TILE_R - 1) / TILE_R)   // 7813
#define GRID_SCORES 148

#define ST_ROW_F 132                    // fp32 staging row: 128 + 4 pad floats
#define ST_ROW_B (ST_ROW_F * 4)         // 528 B
#define ST_BUF_B (TILE_R * ST_ROW_B)    // 33792 B
#define OFF_ST0 0
#define OFF_ST1 ST_BUF_B                // 33792
#define OFF_A16 (2 * ST_BUF_B)          // 67584 : [ks16][row64][16B] = 16384 B
#define OFF_B16 (OFF_A16 + 16384)       // 83968 : [mat2][ks16][n128][16B] = 65536 B
#define OFF_SE  (OFF_B16 + 65536)       // 149504
#define OFF_SACC (OFF_SE + 256)         // 149760
#define SMEM_TOTAL (OFF_SACC + 256)     // 150016

// -------- scratch --------
__device__ float g_E[N_ROWS];
__device__ float g_sumexp;
__device__ float g_wsum[D];

__device__ __forceinline__ uint32_t smem_u32(const void* p) {
    uint32_t a;
    asm("{ .reg .u64 t; cvta.to.shared.u64 t, %1; cvt.u32.u64 %0, t; }" : "=r"(a) : "l"(p));
    return a;
}
__device__ __forceinline__ void mma_f16(float d[4], uint32_t a0, uint32_t a1, uint32_t b) {
    asm volatile(
        "mma.sync.aligned.m16n8k8.row.col.f32.f16.f16.f32 "
        "{%0,%1,%2,%3}, {%4,%5}, {%6}, {%0,%1,%2,%3};"
        : "+f"(d[0]), "+f"(d[1]), "+f"(d[2]), "+f"(d[3])
        : "r"(a0), "r"(a1), "r"(b));
}
__device__ __forceinline__ float tanh_fast(float x) {
    float r;
    asm("tanh.approx.f32 %0, %1;" : "=f"(r) : "f"(x));
    return r;
}
__device__ __forceinline__ uint32_t pack_h2(float lo, float hi) {
    __half2 h = __floats2half2_rn(lo, hi);
    return *(uint32_t*)&h;
}

__device__ __forceinline__ void cp_tile(uint32_t sdst, const float* __restrict__ bag,
                                        int tile, int tid) {
    const int row0 = tile * TILE_R;
    #pragma unroll
    for (int i = 0; i < 8; i++) {
        int chunk = tid + i * 256;
        int row = chunk >> 5, off = chunk & 31;
        int grow = row0 + row;
        int ok = grow < N_ROWS;
        const float* src = bag + (size_t)(ok ? grow : 0) * 128 + off * 4;
        uint32_t dst = sdst + row * ST_ROW_B + off * 16;
        int sz = ok ? 16 : 0;
        asm volatile("cp.async.ca.shared.global [%0], [%1], 16, %2;"
                     :: "r"(dst), "l"(src), "r"(sz) : "memory");
    }
}

__global__ void k_init() {
    int t = threadIdx.x;
    if (t < D) g_wsum[t] = 0.f;
    if (t == 0) g_sumexp = 0.f;
}

// ---------------------------------------------------------------------------
// Persistent: fp16 mma.sync GEMMs (V,U), fp32 accum + gated epilogue + fused
// exp/weighted-bag reduction (reduction reads the fp32 staging tile).
// ---------------------------------------------------------------------------
__global__ void __launch_bounds__(256, 1)
k_scores(const float* __restrict__ bag,
         const float* __restrict__ Wv, const float* __restrict__ bv,
         const float* __restrict__ Wu, const float* __restrict__ bu,
         const float* __restrict__ Ww, const float* __restrict__ bwp)
{
    extern __shared__ __align__(128) char smem[];
    const uint32_t sbase = smem_u32(smem);
    const int tid = threadIdx.x, lane = tid & 31, wid = tid >> 5;
    float* sE   = (float*)(smem + OFF_SE);
    float* sAcc = (float*)(smem + OFF_SACC);

    // ---- repack weights -> fp16 [mat][ks][n][c4 half2]
    for (int idx = tid; idx < 2 * 128 * 16; idx += 256) {
        int mat = idx >> 11, rem = idx & 2047, n = rem >> 4, ks = rem & 15;
        const float* wr = (mat ? Wu : Wv) + n * 128 + ks * 8;
        float4 lo = *(const float4*)(wr);
        float4 hi = *(const float4*)(wr + 4);
        uint4 pk;
        pk.x = pack_h2(lo.x, lo.y);
        pk.y = pack_h2(lo.z, lo.w);
        pk.z = pack_h2(hi.x, hi.y);
        pk.w = pack_h2(hi.z, hi.w);
        *(uint4*)(smem + OFF_B16 + mat * 32768 + ks * 2048 + n * 16) = pk;
    }
    if (tid < 64) sAcc[tid] = 0.f;

    // ---- per-thread epilogue params (fixed h-slice per warp)
    const int r = lane >> 2, c = lane & 3;
    float ww_[2][2], bv_[2][2], bu_[2][2];
    #pragma unroll
    for (int nt = 0; nt < 2; nt++)
        #pragma unroll
        for (int jj = 0; jj < 2; jj++) {
            int h = wid * 16 + nt * 8 + c * 2 + jj;
            ww_[nt][jj] = Ww[h]; bv_[nt][jj] = bv[h]; bu_[nt][jj] = bu[h];
        }
    const float bw0 = bwp[0];
    __syncthreads();

    float esum = 0.f, wsum = 0.f;

    cp_tile(sbase + OFF_ST0, bag, blockIdx.x, tid);
    asm volatile("cp.async.commit_group;" ::: "memory");

    int parity = 0;
    for (int tile = blockIdx.x; tile < NTILES; tile += GRID_SCORES) {
        asm volatile("cp.async.wait_group 0;" ::: "memory");
        __syncthreads();   // stage[parity] ready; A16 free (all warps past prev MMA)

        int nxt = tile + GRID_SCORES;
        if (nxt < NTILES)
            cp_tile(sbase + (parity ? OFF_ST0 : OFF_ST1), bag, nxt, tid);
        asm volatile("cp.async.commit_group;" ::: "memory");

        const char* stage = smem + (parity ? OFF_ST1 : OFF_ST0);

        // ---- convert fp32 stage -> fp16 A16 tile
        {
            const char* a16 = smem + OFF_A16;
            #pragma unroll
            for (int i = 0; i < 16; i++) {
                int task = wid + i * 8;            // 0..127
                int rg = task >> 4, ks = task & 15;
                int row = rg * 8 + r;
                int p = ks * 4 + c;
                float2 f = *(const float2*)(stage + row * ST_ROW_B + p * 8);
                *(uint32_t*)(a16 + ks * 1024 + row * 16 + c * 4) = pack_h2(f.x, f.y);
            }
        }
        __syncthreads();

        // ---- MMA: 16 k-steps (k8), warp tile m64 x n16 x {V,U}
        float accV[4][2][4], accU[4][2][4];
        #pragma unroll
        for (int mt = 0; mt < 4; mt++)
            #pragma unroll
            for (int nt = 0; nt < 2; nt++)
                #pragma unroll
                for (int q = 0; q < 4; q++) { accV[mt][nt][q] = 0.f; accU[mt][nt][q] = 0.f; }

        const char* aBaseF = smem + OFF_A16 + r * 16 + c * 4;
        const char* bBaseF = smem + OFF_B16 + (wid * 16 + r) * 16 + c * 4;
        #pragma unroll 4
        for (int ks = 0; ks < 16; ks++) {
            const char* ak = aBaseF + ks * 1024;
            const char* bk = bBaseF + ks * 2048;
            uint32_t a0[4], a1[4];
            #pragma unroll
            for (int mt = 0; mt < 4; mt++) {
                a0[mt] = *(const uint32_t*)(ak + mt * 256);
                a1[mt] = *(const uint32_t*)(ak + mt * 256 + 128);
            }
            uint32_t bV0 = *(const uint32_t*)(bk);
            uint32_t bV1 = *(const uint32_t*)(bk + 128);
            uint32_t bU0 = *(const uint32_t*)(bk + 32768);
            uint32_t bU1 = *(const uint32_t*)(bk + 32768 + 128);
            #pragma unroll
            for (int mt = 0; mt < 4; mt++) {
                mma_f16(accV[mt][0], a0[mt], a1[mt], bV0);
                mma_f16(accV[mt][1], a0[mt], a1[mt], bV1);
                mma_f16(accU[mt][0], a0[mt], a1[mt], bU0);
                mma_f16(accU[mt][1], a0[mt], a1[mt], bU1);
            }
        }

        // ---- epilogue: gate + Ww dot
        #pragma unroll
        for (int mt = 0; mt < 4; mt++) {
            float slo = 0.f, shi = 0.f;
            #pragma unroll
            for (int nt = 0; nt < 2; nt++)
                #pragma unroll
                for (int jj = 0; jj < 2; jj++) {
                    float v = accV[mt][nt][jj] + bv_[nt][jj];
                    float u = accU[mt][nt][jj] + bu_[nt][jj];
                    float sg = fmaf(0.5f, tanh_fast(0.5f * u), 0.5f);
                    slo = fmaf(ww_[nt][jj] * tanh_fast(v), sg, slo);
                    v = accV[mt][nt][2 + jj] + bv_[nt][jj];
                    u = accU[mt][nt][2 + jj] + bu_[nt][jj];
                    sg = fmaf(0.5f, tanh_fast(0.5f * u), 0.5f);
                    shi = fmaf(ww_[nt][jj] * tanh_fast(v), sg, shi);
                }
            slo += __shfl_xor_sync(0xffffffffu, slo, 1);
            slo += __shfl_xor_sync(0xffffffffu, slo, 2);
            shi += __shfl_xor_sync(0xffffffffu, shi, 1);
            shi += __shfl_xor_sync(0xffffffffu, shi, 2);
            if (c == 0) {
                atomicAdd(&sAcc[mt * 16 + r], slo);
                atomicAdd(&sAcc[mt * 16 + r + 8], shi);
            }
        }
        __syncthreads();

        const int row0 = tile * TILE_R;
        if (tid < 64) {
            int grow = row0 + tid;
            float Araw = sAcc[tid] + bw0;
            sAcc[tid] = 0.f;
            float e = 0.f;
            if (grow < N_ROWS) { e = __expf(Araw); g_E[grow] = e; esum += e; }
            sE[tid] = e;
        }
        __syncthreads();

        // ---- fused weighted-bag reduction (fp32 staging tile)
        if (tid < 128) {
            const float* ap = (const float*)stage + tid;
            float w = 0.f;
            #pragma unroll 8
            for (int rr = 0; rr < TILE_R; rr++) w = fmaf(sE[rr], ap[rr * ST_ROW_F], w);
            wsum += w;
        }
        parity ^= 1;
    }

    // ---- final reductions
    if (tid < 128) atomicAdd(&g_wsum[tid], wsum);
    float s = esum;
    #pragma unroll
    for (int o = 16; o; o >>= 1) s += __shfl_xor_sync(0xffffffffu, s, o);
    if (lane == 0 && s != 0.f) atomicAdd(&g_sumexp, s);
}

__global__ void k_alpha(float* __restrict__ out, const float* __restrict__ b2) {
    int i = blockIdx.x * blockDim.x + threadIdx.x;
    if (i == 0) out[0] = b2[0];
    float invS = __frcp_rn(g_sumexp);
    int j0 = i * 4;
    #pragma unroll
    for (int k = 0; k < 4; k++) {
        int j = j0 + k;
        if (j < N_ROWS) out[1 + j] = g_E[j] * invS;
    }
}

// parallel head: 8 blocks x 8 warps, warp handles 4 outputs; atomicAdd partials
__global__ void k_head(const float* __restrict__ gf,
                       const float* __restrict__ W1, const float* __restrict__ b1,
                       const float* __restrict__ W2, float* __restrict__ out) {
    __shared__ float fused[D + GDIM];
    const int tid = threadIdx.x, lane = tid & 31, wid = tid >> 5;
    const float invS = __frcp_rn(g_sumexp);
    if (tid < D) fused[tid] = g_wsum[tid] * invS;
    else if (tid < D + GDIM) fused[tid] = gf[tid - D];
    __syncthreads();

    float part = 0.f;
    #pragma unroll
    for (int q = 0; q < 4; q++) {
        int m = blockIdx.x * 32 + wid * 4 + q;
        float s = 0.f;
        #pragma unroll
        for (int t = 0; t < 6; t++)
            s = fmaf(W1[m * (D + GDIM) + t * 32 + lane], fused[t * 32 + lane], s);
        #pragma unroll
        for (int o = 16; o; o >>= 1) s += __shfl_xor_sync(0xffffffffu, s, o);
        if (lane == 0) {
            float h = s + b1[m];
            h = h > 0.f ? h : 0.01f * h;
            part = fmaf(h, W2[m], part);
        }
    }
    if (lane == 0) atomicAdd(out, part);
}

extern "C" void kernel_launch(void* const* d_in, const int* in_sizes, int n_in,
                              void* d_out, int out_size)
{
    const float* bag = (const float*)d_in[0];
    const float* gf  = (const float*)d_in[1];
    const float* Wv  = (const float*)d_in[2];
    const float* bv  = (const float*)d_in[3];
    const float* Wu  = (const float*)d_in[4];
    const float* bu  = (const float*)d_in[5];
    const float* Ww  = (const float*)d_in[6];
    const float* bw  = (const float*)d_in[7];
    const float* W1  = (const float*)d_in[8];
    const float* b1  = (const float*)d_in[9];
    const float* W2  = (const float*)d_in[10];
    const float* b2  = (const float*)d_in[11];
    float* out = (float*)d_out;

    cudaFuncSetAttribute(k_scores, cudaFuncAttributeMaxDynamicSharedMemorySize, SMEM_TOTAL);

    k_init<<<1, 256>>>();
    k_scores<<<GRID_SCORES, 256, SMEM_TOTAL>>>(bag, Wv, bv, Wu, bu, Ww, bw);
    k_alpha<<<(N_ROWS + 1023) / 1024, 256>>>(out, b2);
    k_head<<<8, 256>>>(gf, W1, b1, W2, out);
}

// round 5
// speedup vs baseline: 1.6478x; 1.6478x over previous
#include <cuda_runtime.h>
#include <math.h>
#include <stdint.h>

#define N_ROWS 500000
#define D 128
#define H 128
#define GDIM 64
#define M 256
#define TILE_R 64
#define NTILES ((N_ROWS + TILE_R - 1) / TILE_R)   // 7813
#define GRID_SCORES 148

#define A_ROW_F 132                   // 128 floats + 4 pad (conflict-free frag loads)
#define A_ROW_B (A_ROW_F * 4)         // 528 B (16B-aligned)
#define A_BUF_B (TILE_R * A_ROW_B)    // 33792 B
#define OFF_A0 0
#define OFF_A1 A_BUF_B
#define OFF_B  (2 * A_BUF_B)          // 67584
#define B_MAT_B 65536                 // per-matrix packed tf32: [ks16][n128][c4] float2
#define OFF_SE   (OFF_B + 2 * B_MAT_B)   // 198656
#define OFF_SACC (OFF_SE + 256)          // 198912
#define SMEM_TOTAL (OFF_SACC + 256)      // 199168

// -------- scratch --------
__device__ float g_E[N_ROWS];
__device__ float g_sumexp;
__device__ float g_wsum[D];

__device__ __forceinline__ uint32_t smem_u32(const void* p) {
    uint32_t a;
    asm("{ .reg .u64 t; cvta.to.shared.u64 t, %1; cvt.u32.u64 %0, t; }" : "=r"(a) : "l"(p));
    return a;
}
__device__ __forceinline__ uint32_t f2tf32(float f) {
    uint32_t r;
    asm("cvt.rna.tf32.f32 %0, %1;" : "=r"(r) : "f"(f));
    return r;
}
__device__ __forceinline__ void mma_tf32(float d[4], const uint32_t a[4], uint2 b) {
    asm volatile(
        "mma.sync.aligned.m16n8k8.row.col.f32.tf32.tf32.f32 "
        "{%0,%1,%2,%3}, {%4,%5,%6,%7}, {%8,%9}, {%0,%1,%2,%3};"
        : "+f"(d[0]), "+f"(d[1]), "+f"(d[2]), "+f"(d[3])
        : "r"(a[0]), "r"(a[1]), "r"(a[2]), "r"(a[3]), "r"(b.x), "r"(b.y));
}
__device__ __forceinline__ float tanh_fast(float x) {
    float r;
    asm("tanh.approx.f32 %0, %1;" : "=f"(r) : "f"(x));
    return r;
}

__device__ __forceinline__ void cp_tile(uint32_t sdst, const float* __restrict__ bag,
                                        int tile, int tid) {
    const int row0 = tile * TILE_R;
    #pragma unroll
    for (int i = 0; i < 8; i++) {
        int chunk = tid + i * 256;
        int row = chunk >> 5, off = chunk & 31;
        int grow = row0 + row;
        int ok = grow < N_ROWS;
        const float* src = bag + (size_t)(ok ? grow : 0) * 128 + off * 4;
        uint32_t dst = sdst + row * A_ROW_B + off * 16;
        int sz = ok ? 16 : 0;
        asm volatile("cp.async.ca.shared.global [%0], [%1], 16, %2;"
                     :: "r"(dst), "l"(src), "r"(sz) : "memory");
    }
}

__global__ void k_init() {
    int t = threadIdx.x;
    if (t < D) g_wsum[t] = 0.f;
    if (t == 0) g_sumexp = 0.f;
}

// ---------------------------------------------------------------------------
// Persistent: tf32 mma.sync GEMMs (V,U) + gated epilogue + fused exp/wsum
// (identical to the measured 225us R3 implementation)
// ---------------------------------------------------------------------------
__global__ void __launch_bounds__(256, 1)
k_scores(const float* __restrict__ bag,
         const float* __restrict__ Wv, const float* __restrict__ bv,
         const float* __restrict__ Wu, const float* __restrict__ bu,
         const float* __restrict__ Ww, const float* __restrict__ bwp)
{
    extern __shared__ __align__(128) char smem[];
    const uint32_t sbase = smem_u32(smem);
    const int tid = threadIdx.x, lane = tid & 31, wid = tid >> 5;
    float* sE   = (float*)(smem + OFF_SE);
    float* sAcc = (float*)(smem + OFF_SACC);

    // ---- repack weights -> tf32 packed [mat][ks][n][c] float2{W[n][ks8+c], W[n][ks8+c+4]}
    for (int idx = tid; idx < 2 * 128 * 16; idx += 256) {
        int mat = idx >> 11, rem = idx & 2047, n = rem >> 4, ks = rem & 15;
        const float* wr = (mat ? Wu : Wv) + n * 128 + ks * 8;
        float4 lo = *(const float4*)(wr);
        float4 hi = *(const float4*)(wr + 4);
        uint4* dst = (uint4*)(smem + OFF_B + mat * B_MAT_B + ks * 4096 + n * 32);
        dst[0] = make_uint4(f2tf32(lo.x), f2tf32(hi.x), f2tf32(lo.y), f2tf32(hi.y));
        dst[1] = make_uint4(f2tf32(lo.z), f2tf32(hi.z), f2tf32(lo.w), f2tf32(hi.w));
    }
    if (tid < 64) sAcc[tid] = 0.f;

    // ---- per-thread epilogue params (fixed h-slice per warp)
    const int r = lane >> 2, c = lane & 3;
    float ww_[2][2], bv_[2][2], bu_[2][2];
    #pragma unroll
    for (int nt = 0; nt < 2; nt++)
        #pragma unroll
        for (int jj = 0; jj < 2; jj++) {
            int h = wid * 16 + nt * 8 + c * 2 + jj;
            ww_[nt][jj] = Ww[h]; bv_[nt][jj] = bv[h]; bu_[nt][jj] = bu[h];
        }
    const float bw0 = bwp[0];
    __syncthreads();

    float esum = 0.f, wsum = 0.f;

    cp_tile(sbase + OFF_A0, bag, blockIdx.x, tid);
    asm volatile("cp.async.commit_group;" ::: "memory");

    int parity = 0;
    for (int tile = blockIdx.x; tile < NTILES; tile += GRID_SCORES) {
        asm volatile("cp.async.wait_group 0;" ::: "memory");
        __syncthreads();

        int nxt = tile + GRID_SCORES;
        if (nxt < NTILES) cp_tile(sbase + (parity ? OFF_A0 : OFF_A1), bag, nxt, tid);
        asm volatile("cp.async.commit_group;" ::: "memory");

        const char* aBase = smem + (parity ? OFF_A1 : OFF_A0);

        float accV[4][2][4], accU[4][2][4];
        #pragma unroll
        for (int mt = 0; mt < 4; mt++)
            #pragma unroll
            for (int nt = 0; nt < 2; nt++)
                #pragma unroll
                for (int q = 0; q < 4; q++) { accV[mt][nt][q] = 0.f; accU[mt][nt][q] = 0.f; }

        #pragma unroll 4
        for (int ks = 0; ks < 16; ks++) {
            uint32_t a[4][4];
            #pragma unroll
            for (int mt = 0; mt < 4; mt++) {
                const float* ap = (const float*)aBase + (mt * 16 + r) * A_ROW_F + ks * 8 + c;
                a[mt][0] = __float_as_uint(ap[0]);
                a[mt][1] = __float_as_uint(ap[8 * A_ROW_F]);
                a[mt][2] = __float_as_uint(ap[4]);
                a[mt][3] = __float_as_uint(ap[8 * A_ROW_F + 4]);
            }
            const char* bslab = smem + OFF_B + ks * 4096 + (wid * 16 + r) * 32 + c * 8;
            uint2 bV[2], bU[2];
            bV[0] = *(const uint2*)(bslab);
            bV[1] = *(const uint2*)(bslab + 256);
            bU[0] = *(const uint2*)(bslab + B_MAT_B);
            bU[1] = *(const uint2*)(bslab + B_MAT_B + 256);
            #pragma unroll
            for (int mt = 0; mt < 4; mt++) {
                mma_tf32(accV[mt][0], a[mt], bV[0]);
                mma_tf32(accV[mt][1], a[mt], bV[1]);
                mma_tf32(accU[mt][0], a[mt], bU[0]);
                mma_tf32(accU[mt][1], a[mt], bU[1]);
            }
        }

        // ---- epilogue: gate + Ww dot (thread pairs V/U fragments directly)
        #pragma unroll
        for (int mt = 0; mt < 4; mt++) {
            float slo = 0.f, shi = 0.f;
            #pragma unroll
            for (int nt = 0; nt < 2; nt++)
                #pragma unroll
                for (int jj = 0; jj < 2; jj++) {
                    float v = accV[mt][nt][jj] + bv_[nt][jj];
                    float u = accU[mt][nt][jj] + bu_[nt][jj];
                    float sg = fmaf(0.5f, tanh_fast(0.5f * u), 0.5f);
                    slo = fmaf(ww_[nt][jj] * tanh_fast(v), sg, slo);
                    v = accV[mt][nt][2 + jj] + bv_[nt][jj];
                    u = accU[mt][nt][2 + jj] + bu_[nt][jj];
                    sg = fmaf(0.5f, tanh_fast(0.5f * u), 0.5f);
                    shi = fmaf(ww_[nt][jj] * tanh_fast(v), sg, shi);
                }
            slo += __shfl_xor_sync(0xffffffffu, slo, 1);
            slo += __shfl_xor_sync(0xffffffffu, slo, 2);
            shi += __shfl_xor_sync(0xffffffffu, shi, 1);
            shi += __shfl_xor_sync(0xffffffffu, shi, 2);
            if (c == 0) {
                atomicAdd(&sAcc[mt * 16 + r], slo);
                atomicAdd(&sAcc[mt * 16 + r + 8], shi);
            }
        }
        __syncthreads();

        const int row0 = tile * TILE_R;
        if (tid < 64) {
            int grow = row0 + tid;
            float Araw = sAcc[tid] + bw0;
            sAcc[tid] = 0.f;
            float e = 0.f;
            if (grow < N_ROWS) { e = __expf(Araw); g_E[grow] = e; esum += e; }
            sE[tid] = e;
        }
        __syncthreads();

        // ---- fused weighted-bag reduction from the SMEM tile
        if (tid < 128) {
            const float* ap = (const float*)aBase + tid;
            float w = 0.f;
            #pragma unroll 8
            for (int rr = 0; rr < TILE_R; rr++) w = fmaf(sE[rr], ap[rr * A_ROW_F], w);
            wsum += w;
        }
        parity ^= 1;
    }

    // ---- final reductions
    if (tid < 128) atomicAdd(&g_wsum[tid], wsum);
    float s = esum;
    #pragma unroll
    for (int o = 16; o; o >>= 1) s += __shfl_xor_sync(0xffffffffu, s, o);
    if (lane == 0 && s != 0.f) atomicAdd(&g_sumexp, s);
}

__global__ void k_alpha(float* __restrict__ out, const float* __restrict__ b2) {
    int i = blockIdx.x * blockDim.x + threadIdx.x;
    if (i == 0) out[0] = b2[0];
    float invS = __frcp_rn(g_sumexp);
    int j0 = i * 2;
    #pragma unroll
    for (int k = 0; k < 2; k++) {
        int j = j0 + k;
        if (j < N_ROWS) out[1 + j] = g_E[j] * invS;
    }
}

// parallel head: 8 blocks x 8 warps, warp handles 4 outputs; atomicAdd partials
__global__ void k_head(const float* __restrict__ gf,
                       const float* __restrict__ W1, const float* __restrict__ b1,
                       const float* __restrict__ W2, float* __restrict__ out) {
    __shared__ float fused[D + GDIM];
    const int tid = threadIdx.x, lane = tid & 31, wid = tid >> 5;
    const float invS = __frcp_rn(g_sumexp);
    if (tid < D) fused[tid] = g_wsum[tid] * invS;
    else if (tid < D + GDIM) fused[tid] = gf[tid - D];
    __syncthreads();

    float part = 0.f;
    #pragma unroll
    for (int q = 0; q < 4; q++) {
        int m = blockIdx.x * 32 + wid * 4 + q;
        float s = 0.f;
        #pragma unroll
        for (int t = 0; t < 6; t++)
            s = fmaf(W1[m * (D + GDIM) + t * 32 + lane], fused[t * 32 + lane], s);
        #pragma unroll
        for (int o = 16; o; o >>= 1) s += __shfl_xor_sync(0xffffffffu, s, o);
        if (lane == 0) {
            float h = s + b1[m];
            h = h > 0.f ? h : 0.01f * h;
            part = fmaf(h, W2[m], part);
        }
    }
    if (lane == 0) atomicAdd(out, part);
}

extern "C" void kernel_launch(void* const* d_in, const int* in_sizes, int n_in,
                              void* d_out, int out_size)
{
    const float* bag = (const float*)d_in[0];
    const float* gf  = (const float*)d_in[1];
    const float* Wv  = (const float*)d_in[2];
    const float* bv  = (const float*)d_in[3];
    const float* Wu  = (const float*)d_in[4];
    const float* bu  = (const float*)d_in[5];
    const float* Ww  = (const float*)d_in[6];
    const float* bw  = (const float*)d_in[7];
    const float* W1  = (const float*)d_in[8];
    const float* b1  = (const float*)d_in[9];
    const float* W2  = (const float*)d_in[10];
    const float* b2  = (const float*)d_in[11];
    float* out = (float*)d_out;

    cudaFuncSetAttribute(k_scores, cudaFuncAttributeMaxDynamicSharedMemorySize, SMEM_TOTAL);

    k_init<<<1, 256>>>();
    k_scores<<<GRID_SCORES, 256, SMEM_TOTAL>>>(bag, Wv, bv, Wu, bu, Ww, bw);
    k_alpha<<<(N_ROWS + 511) / 512, 256>>>(out, b2);
    k_head<<<8, 256>>>(gf, W1, b1, W2, out);
}

// round 6
// speedup vs baseline: 1.6489x; 1.0007x over previous
#include <cuda_runtime.h>
#include <math.h>
#include <stdint.h>

#define N_ROWS 500000
#define D 128
#define H 128
#define GDIM 64
#define M 256
#define TILE_R 64
#define NTILES ((N_ROWS + TILE_R - 1) / TILE_R)   // 7813
#define GRID_SCORES 148

#define A_ROW_F 132                   // 128 floats + 4 pad (conflict-free frag loads)
#define A_ROW_B (A_ROW_F * 4)         // 528 B (16B-aligned)
#define A_BUF_B (TILE_R * A_ROW_B)    // 33792 B
#define OFF_A0 0
#define OFF_A1 A_BUF_B
#define OFF_B  (2 * A_BUF_B)          // 67584
#define B_MAT_B 65536                 // per-matrix packed tf32: [ks16][n128][c4] float2
#define OFF_SE   (OFF_B + 2 * B_MAT_B)   // 198656
#define OFF_SACC (OFF_SE + 256)          // 198912
#define SMEM_TOTAL (OFF_SACC + 256)      // 199168

// -------- scratch --------
__device__ float g_E[N_ROWS];
__device__ float g_sumexp;
__device__ float g_wsum[D];

__device__ __forceinline__ uint32_t smem_u32(const void* p) {
    uint32_t a;
    asm("{ .reg .u64 t; cvta.to.shared.u64 t, %1; cvt.u32.u64 %0, t; }" : "=r"(a) : "l"(p));
    return a;
}
__device__ __forceinline__ uint32_t f2tf32(float f) {
    uint32_t r;
    asm("cvt.rna.tf32.f32 %0, %1;" : "=r"(r) : "f"(f));
    return r;
}
__device__ __forceinline__ void mma_tf32(float d[4], const uint32_t a[4], uint2 b) {
    asm volatile(
        "mma.sync.aligned.m16n8k8.row.col.f32.tf32.tf32.f32 "
        "{%0,%1,%2,%3}, {%4,%5,%6,%7}, {%8,%9}, {%0,%1,%2,%3};"
        : "+f"(d[0]), "+f"(d[1]), "+f"(d[2]), "+f"(d[3])
        : "r"(a[0]), "r"(a[1]), "r"(a[2]), "r"(a[3]), "r"(b.x), "r"(b.y));
}
__device__ __forceinline__ float tanh_fast(float x) {
    float r;
    asm("tanh.approx.f32 %0, %1;" : "=f"(r) : "f"(x));
    return r;
}

__device__ __forceinline__ void cp_tile(uint32_t sdst, const float* __restrict__ bag,
                                        int tile, int tid) {
    const int row0 = tile * TILE_R;
    #pragma unroll
    for (int i = 0; i < 8; i++) {
        int chunk = tid + i * 256;
        int row = chunk >> 5, off = chunk & 31;
        int grow = row0 + row;
        int ok = grow < N_ROWS;
        const float* src = bag + (size_t)(ok ? grow : 0) * 128 + off * 4;
        uint32_t dst = sdst + row * A_ROW_B + off * 16;
        int sz = ok ? 16 : 0;
        asm volatile("cp.async.ca.shared.global [%0], [%1], 16, %2;"
                     :: "r"(dst), "l"(src), "r"(sz) : "memory");
    }
}

__global__ void k_init() {
    int t = threadIdx.x;
    if (t < D) g_wsum[t] = 0.f;
    if (t == 0) g_sumexp = 0.f;
}

// ---------------------------------------------------------------------------
// Persistent: tf32 mma.sync GEMMs (V,U) + gated epilogue + fused exp/wsum
// (identical to the measured 225us R3 implementation)
// ---------------------------------------------------------------------------
__global__ void __launch_bounds__(256, 1)
k_scores(const float* __restrict__ bag,
         const float* __restrict__ Wv, const float* __restrict__ bv,
         const float* __restrict__ Wu, const float* __restrict__ bu,
         const float* __restrict__ Ww, const float* __restrict__ bwp)
{
    extern __shared__ __align__(128) char smem[];
    const uint32_t sbase = smem_u32(smem);
    const int tid = threadIdx.x, lane = tid & 31, wid = tid >> 5;
    float* sE   = (float*)(smem + OFF_SE);
    float* sAcc = (float*)(smem + OFF_SACC);

    // ---- repack weights -> tf32 packed [mat][ks][n][c] float2{W[n][ks8+c], W[n][ks8+c+4]}
    for (int idx = tid; idx < 2 * 128 * 16; idx += 256) {
        int mat = idx >> 11, rem = idx & 2047, n = rem >> 4, ks = rem & 15;
        const float* wr = (mat ? Wu : Wv) + n * 128 + ks * 8;
        float4 lo = *(const float4*)(wr);
        float4 hi = *(const float4*)(wr + 4);
        uint4* dst = (uint4*)(smem + OFF_B + mat * B_MAT_B + ks * 4096 + n * 32);
        dst[0] = make_uint4(f2tf32(lo.x), f2tf32(hi.x), f2tf32(lo.y), f2tf32(hi.y));
        dst[1] = make_uint4(f2tf32(lo.z), f2tf32(hi.z), f2tf32(lo.w), f2tf32(hi.w));
    }
    if (tid < 64) sAcc[tid] = 0.f;

    // ---- per-thread epilogue params (fixed h-slice per warp)
    const int r = lane >> 2, c = lane & 3;
    float ww_[2][2], bv_[2][2], bu_[2][2];
    #pragma unroll
    for (int nt = 0; nt < 2; nt++)
        #pragma unroll
        for (int jj = 0; jj < 2; jj++) {
            int h = wid * 16 + nt * 8 + c * 2 + jj;
            ww_[nt][jj] = Ww[h]; bv_[nt][jj] = bv[h]; bu_[nt][jj] = bu[h];
        }
    const float bw0 = bwp[0];
    __syncthreads();

    float esum = 0.f, wsum = 0.f;

    cp_tile(sbase + OFF_A0, bag, blockIdx.x, tid);
    asm volatile("cp.async.commit_group;" ::: "memory");

    int parity = 0;
    for (int tile = blockIdx.x; tile < NTILES; tile += GRID_SCORES) {
        asm volatile("cp.async.wait_group 0;" ::: "memory");
        __syncthreads();

        int nxt = tile + GRID_SCORES;
        if (nxt < NTILES) cp_tile(sbase + (parity ? OFF_A0 : OFF_A1), bag, nxt, tid);
        asm volatile("cp.async.commit_group;" ::: "memory");

        const char* aBase = smem + (parity ? OFF_A1 : OFF_A0);

        float accV[4][2][4], accU[4][2][4];
        #pragma unroll
        for (int mt = 0; mt < 4; mt++)
            #pragma unroll
            for (int nt = 0; nt < 2; nt++)
                #pragma unroll
                for (int q = 0; q < 4; q++) { accV[mt][nt][q] = 0.f; accU[mt][nt][q] = 0.f; }

        #pragma unroll 4
        for (int ks = 0; ks < 16; ks++) {
            uint32_t a[4][4];
            #pragma unroll
            for (int mt = 0; mt < 4; mt++) {
                const float* ap = (const float*)aBase + (mt * 16 + r) * A_ROW_F + ks * 8 + c;
                a[mt][0] = __float_as_uint(ap[0]);
                a[mt][1] = __float_as_uint(ap[8 * A_ROW_F]);
                a[mt][2] = __float_as_uint(ap[4]);
                a[mt][3] = __float_as_uint(ap[8 * A_ROW_F + 4]);
            }
            const char* bslab = smem + OFF_B + ks * 4096 + (wid * 16 + r) * 32 + c * 8;
            uint2 bV[2], bU[2];
            bV[0] = *(const uint2*)(bslab);
            bV[1] = *(const uint2*)(bslab + 256);
            bU[0] = *(const uint2*)(bslab + B_MAT_B);
            bU[1] = *(const uint2*)(bslab + B_MAT_B + 256);
            #pragma unroll
            for (int mt = 0; mt < 4; mt++) {
                mma_tf32(accV[mt][0], a[mt], bV[0]);
                mma_tf32(accV[mt][1], a[mt], bV[1]);
                mma_tf32(accU[mt][0], a[mt], bU[0]);
                mma_tf32(accU[mt][1], a[mt], bU[1]);
            }
        }

        // ---- epilogue: gate + Ww dot (thread pairs V/U fragments directly)
        #pragma unroll
        for (int mt = 0; mt < 4; mt++) {
            float slo = 0.f, shi = 0.f;
            #pragma unroll
            for (int nt = 0; nt < 2; nt++)
                #pragma unroll
                for (int jj = 0; jj < 2; jj++) {
                    float v = accV[mt][nt][jj] + bv_[nt][jj];
                    float u = accU[mt][nt][jj] + bu_[nt][jj];
                    float sg = fmaf(0.5f, tanh_fast(0.5f * u), 0.5f);
                    slo = fmaf(ww_[nt][jj] * tanh_fast(v), sg, slo);
                    v = accV[mt][nt][2 + jj] + bv_[nt][jj];
                    u = accU[mt][nt][2 + jj] + bu_[nt][jj];
                    sg = fmaf(0.5f, tanh_fast(0.5f * u), 0.5f);
                    shi = fmaf(ww_[nt][jj] * tanh_fast(v), sg, shi);
                }
            slo += __shfl_xor_sync(0xffffffffu, slo, 1);
            slo += __shfl_xor_sync(0xffffffffu, slo, 2);
            shi += __shfl_xor_sync(0xffffffffu, shi, 1);
            shi += __shfl_xor_sync(0xffffffffu, shi, 2);
            if (c == 0) {
                atomicAdd(&sAcc[mt * 16 + r], slo);
                atomicAdd(&sAcc[mt * 16 + r + 8], shi);
            }
        }
        __syncthreads();

        const int row0 = tile * TILE_R;
        if (tid < 64) {
            int grow = row0 + tid;
            float Araw = sAcc[tid] + bw0;
            sAcc[tid] = 0.f;
            float e = 0.f;
            if (grow < N_ROWS) { e = __expf(Araw); g_E[grow] = e; esum += e; }
            sE[tid] = e;
        }
        __syncthreads();

        // ---- fused weighted-bag reduction from the SMEM tile
        if (tid < 128) {
            const float* ap = (const float*)aBase + tid;
            float w = 0.f;
            #pragma unroll 8
            for (int rr = 0; rr < TILE_R; rr++) w = fmaf(sE[rr], ap[rr * A_ROW_F], w);
            wsum += w;
        }
        parity ^= 1;
    }

    // ---- final reductions
    if (tid < 128) atomicAdd(&g_wsum[tid], wsum);
    float s = esum;
    #pragma unroll
    for (int o = 16; o; o >>= 1) s += __shfl_xor_sync(0xffffffffu, s, o);
    if (lane == 0 && s != 0.f) atomicAdd(&g_sumexp, s);
}

__global__ void k_alpha(float* __restrict__ out, const float* __restrict__ b2) {
    int i = blockIdx.x * blockDim.x + threadIdx.x;
    if (i == 0) out[0] = b2[0];
    float invS = __frcp_rn(g_sumexp);
    int j0 = i * 2;
    #pragma unroll
    for (int k = 0; k < 2; k++) {
        int j = j0 + k;
        if (j < N_ROWS) out[1 + j] = g_E[j] * invS;
    }
}

// parallel head: 8 blocks x 8 warps, warp handles 4 outputs; atomicAdd partials
__global__ void k_head(const float* __restrict__ gf,
                       const float* __restrict__ W1, const float* __restrict__ b1,
                       const float* __restrict__ W2, float* __restrict__ out) {
    __shared__ float fused[D + GDIM];
    const int tid = threadIdx.x, lane = tid & 31, wid = tid >> 5;
    const float invS = __frcp_rn(g_sumexp);
    if (tid < D) fused[tid] = g_wsum[tid] * invS;
    else if (tid < D + GDIM) fused[tid] = gf[tid - D];
    __syncthreads();

    float part = 0.f;
    #pragma unroll
    for (int q = 0; q < 4; q++) {
        int m = blockIdx.x * 32 + wid * 4 + q;
        float s = 0.f;
        #pragma unroll
        for (int t = 0; t < 6; t++)
            s = fmaf(W1[m * (D + GDIM) + t * 32 + lane], fused[t * 32 + lane], s);
        #pragma unroll
        for (int o = 16; o; o >>= 1) s += __shfl_xor_sync(0xffffffffu, s, o);
        if (lane == 0) {
            float h = s + b1[m];
            h = h > 0.f ? h : 0.01f * h;
            part = fmaf(h, W2[m], part);
        }
    }
    if (lane == 0) atomicAdd(out, part);
}

extern "C" void kernel_launch(void* const* d_in, const int* in_sizes, int n_in,
                              void* d_out, int out_size)
{
    const float* bag = (const float*)d_in[0];
    const float* gf  = (const float*)d_in[1];
    const float* Wv  = (const float*)d_in[2];
    const float* bv  = (const float*)d_in[3];
    const float* Wu  = (const float*)d_in[4];
    const float* bu  = (const float*)d_in[5];
    const float* Ww  = (const float*)d_in[6];
    const float* bw  = (const float*)d_in[7];
    const float* W1  = (const float*)d_in[8];
    const float* b1  = (const float*)d_in[9];
    const float* W2  = (const float*)d_in[10];
    const float* b2  = (const float*)d_in[11];
    float* out = (float*)d_out;

    cudaFuncSetAttribute(k_scores, cudaFuncAttributeMaxDynamicSharedMemorySize, SMEM_TOTAL);

    k_init<<<1, 256>>>();
    k_scores<<<GRID_SCORES, 256, SMEM_TOTAL>>>(bag, Wv, bv, Wu, bu, Ww, bw);
    k_alpha<<<(N_ROWS + 511) / 512, 256>>>(out, b2);
    k_head<<<8, 256>>>(gf, W1, b1, W2, out);
}

// round 7
// speedup vs baseline: 1.7533x; 1.0633x over previous
#include <cuda_runtime.h>
#include <cuda_fp16.h>
#include <math.h>
#include <stdint.h>

#define N_ROWS 500000
#define D 128
#define H 128
#define GDIM 64
#define M 256
#define TILE_R 128
#define NTILES ((N_ROWS + TILE_R - 1) / TILE_R)   // 3907
#define GRID_SCORES 148

// fp16 staging: row = 128 halves + 8 pad = 272 B (row*68 floats -> bank r*4 pattern)
#define ST_ROW_B 272
#define ST_BUF_B (TILE_R * ST_ROW_B)     // 34816
#define OFF_ST0 0
#define OFF_ST1 ST_BUF_B                 // 34816
// B16: [mat2][ks8][n128][48B: 16 halves + 8 pad]  (n*12 floats -> distinct banks)
#define B_MAT_B (8 * 128 * 48)           // 49152
#define OFF_B16 (2 * ST_BUF_B)           // 69632
#define OFF_SE   (OFF_B16 + 2 * B_MAT_B) // 167936
#define OFF_SACC (OFF_SE + 512)          // 168448
#define SMEM_TOTAL (OFF_SACC + 512)      // 168960

// -------- scratch --------
__device__ float g_E[N_ROWS];
__device__ float g_sumexp;
__device__ float g_wsum[D];

__device__ __forceinline__ void mma_f16_k16(float d[4], const uint32_t a[4], uint32_t b0, uint32_t b1) {
    asm volatile(
        "mma.sync.aligned.m16n8k16.row.col.f32.f16.f16.f32 "
        "{%0,%1,%2,%3}, {%4,%5,%6,%7}, {%8,%9}, {%0,%1,%2,%3};"
        : "+f"(d[0]), "+f"(d[1]), "+f"(d[2]), "+f"(d[3])
        : "r"(a[0]), "r"(a[1]), "r"(a[2]), "r"(a[3]), "r"(b0), "r"(b1));
}
__device__ __forceinline__ float tanh_fast(float x) {
    float r;
    asm("tanh.approx.f32 %0, %1;" : "=f"(r) : "f"(x));
    return r;
}
__device__ __forceinline__ uint32_t pack_h2(float lo, float hi) {
    __half2 h = __floats2half2_rn(lo, hi);
    return *(uint32_t*)&h;
}

__global__ void k_init() {
    int t = threadIdx.x;
    if (t < D) g_wsum[t] = 0.f;
    if (t == 0) g_sumexp = 0.f;
}

// load one 128-row tile: gmem fp32 -> cvt fp16 -> smem stage
__device__ __forceinline__ void load_tile_f16(char* stage, const float* __restrict__ bag,
                                              int tile, int tid) {
    const int row0 = tile * TILE_R;
    #pragma unroll 4
    for (int i = 0; i < 16; i++) {
        int chunk = tid + i * 256;          // 0..4095
        int row = chunk >> 5, c4 = chunk & 31;
        int grow = row0 + row;
        float4 v = make_float4(0.f, 0.f, 0.f, 0.f);
        if (grow < N_ROWS) v = ((const float4*)bag)[grow * 32 + c4];
        uint2 pk = make_uint2(pack_h2(v.x, v.y), pack_h2(v.z, v.w));
        *(uint2*)(stage + row * ST_ROW_B + c4 * 8) = pk;
    }
}

// ---------------------------------------------------------------------------
// Persistent: fp16 m16n8k16 GEMMs (V,U), fp32 accum, gated epilogue,
// fused exp + weighted-bag reduction. 128-row tiles, two 64-row m-groups.
// ---------------------------------------------------------------------------
__global__ void __launch_bounds__(256, 1)
k_scores(const float* __restrict__ bag,
         const float* __restrict__ Wv, const float* __restrict__ bv,
         const float* __restrict__ Wu, const float* __restrict__ bu,
         const float* __restrict__ Ww, const float* __restrict__ bwp)
{
    extern __shared__ __align__(128) char smem[];
    const int tid = threadIdx.x, lane = tid & 31, wid = tid >> 5;
    float* sE   = (float*)(smem + OFF_SE);
    float* sAcc = (float*)(smem + OFF_SACC);

    // ---- repack weights -> fp16 [mat][ks8][n][16 halves + pad]
    for (int idx = tid; idx < 2 * 128 * 8; idx += 256) {
        int mat = idx >> 10, n = (idx >> 3) & 127, ks = idx & 7;
        const float* wr = (mat ? Wu : Wv) + n * 128 + ks * 16;
        float4 f0 = *(const float4*)(wr);
        float4 f1 = *(const float4*)(wr + 4);
        float4 f2 = *(const float4*)(wr + 8);
        float4 f3 = *(const float4*)(wr + 12);
        char* dst = smem + OFF_B16 + mat * B_MAT_B + ks * 6144 + n * 48;
        *(uint4*)(dst)      = make_uint4(pack_h2(f0.x, f0.y), pack_h2(f0.z, f0.w),
                                         pack_h2(f1.x, f1.y), pack_h2(f1.z, f1.w));
        *(uint4*)(dst + 16) = make_uint4(pack_h2(f2.x, f2.y), pack_h2(f2.z, f2.w),
                                         pack_h2(f3.x, f3.y), pack_h2(f3.z, f3.w));
    }
    if (tid < TILE_R) sAcc[tid] = 0.f;

    // ---- per-thread epilogue params (h = wid*16 + nt*8 + c*2 + jj)
    const int r = lane >> 2, c = lane & 3;
    float ww_[2][2], bv_[2][2], bu_[2][2];
    #pragma unroll
    for (int nt = 0; nt < 2; nt++)
        #pragma unroll
        for (int jj = 0; jj < 2; jj++) {
            int h = wid * 16 + nt * 8 + c * 2 + jj;
            ww_[nt][jj] = Ww[h]; bv_[nt][jj] = bv[h]; bu_[nt][jj] = bu[h];
        }
    const float bw0 = bwp[0];

    // prologue: load first tile into stage0 (no sync needed yet; sync below)
    load_tile_f16(smem + OFF_ST0, bag, blockIdx.x, tid);

    float esum = 0.f, ws0 = 0.f, ws1 = 0.f;

    int parity = 0;
    for (int tile = blockIdx.x; tile < NTILES; tile += GRID_SCORES) {
        __syncthreads();   // stage[parity] fully written; sAcc zeroed; B16 ready (1st iter)
        char* stage = smem + (parity ? OFF_ST1 : OFF_ST0);

        // ---- two 64-row m-groups
        #pragma unroll
        for (int mg = 0; mg < 2; mg++) {
            float accV[4][2][4], accU[4][2][4];
            #pragma unroll
            for (int mt = 0; mt < 4; mt++)
                #pragma unroll
                for (int nt = 0; nt < 2; nt++)
                    #pragma unroll
                    for (int q = 0; q < 4; q++) { accV[mt][nt][q] = 0.f; accU[mt][nt][q] = 0.f; }

            const char* aB = stage + (mg * 64 + r) * ST_ROW_B + c * 4;
            const char* bB = smem + OFF_B16 + (wid * 16 + r) * 48 + c * 4;

            #pragma unroll
            for (int ks = 0; ks < 8; ks++) {
                uint32_t a[4][4];
                #pragma unroll
                for (int mt = 0; mt < 4; mt++) {
                    const char* ap = aB + mt * 16 * ST_ROW_B + ks * 32;
                    a[mt][0] = *(const uint32_t*)(ap);
                    a[mt][1] = *(const uint32_t*)(ap + 8 * ST_ROW_B);
                    a[mt][2] = *(const uint32_t*)(ap + 16);
                    a[mt][3] = *(const uint32_t*)(ap + 8 * ST_ROW_B + 16);
                }
                const char* bk = bB + ks * 6144;
                uint32_t bV0[2], bV1[2], bU0[2], bU1[2];
                #pragma unroll
                for (int nt = 0; nt < 2; nt++) {
                    const char* bn = bk + nt * 8 * 48;
                    bV0[nt] = *(const uint32_t*)(bn);
                    bV1[nt] = *(const uint32_t*)(bn + 16);
                    bU0[nt] = *(const uint32_t*)(bn + B_MAT_B);
                    bU1[nt] = *(const uint32_t*)(bn + B_MAT_B + 16);
                }
                #pragma unroll
                for (int mt = 0; mt < 4; mt++) {
                    mma_f16_k16(accV[mt][0], a[mt], bV0[0], bV1[0]);
                    mma_f16_k16(accV[mt][1], a[mt], bV0[1], bV1[1]);
                    mma_f16_k16(accU[mt][0], a[mt], bU0[0], bU1[0]);
                    mma_f16_k16(accU[mt][1], a[mt], bU0[1], bU1[1]);
                }
            }

            // ---- epilogue: gate + Ww partial dot
            #pragma unroll
            for (int mt = 0; mt < 4; mt++) {
                float slo = 0.f, shi = 0.f;
                #pragma unroll
                for (int nt = 0; nt < 2; nt++)
                    #pragma unroll
                    for (int jj = 0; jj < 2; jj++) {
                        float v = accV[mt][nt][jj] + bv_[nt][jj];
                        float u = accU[mt][nt][jj] + bu_[nt][jj];
                        float sg = fmaf(0.5f, tanh_fast(0.5f * u), 0.5f);
                        slo = fmaf(ww_[nt][jj] * tanh_fast(v), sg, slo);
                        v = accV[mt][nt][2 + jj] + bv_[nt][jj];
                        u = accU[mt][nt][2 + jj] + bu_[nt][jj];
                        sg = fmaf(0.5f, tanh_fast(0.5f * u), 0.5f);
                        shi = fmaf(ww_[nt][jj] * tanh_fast(v), sg, shi);
                    }
                slo += __shfl_xor_sync(0xffffffffu, slo, 1);
                slo += __shfl_xor_sync(0xffffffffu, slo, 2);
                shi += __shfl_xor_sync(0xffffffffu, shi, 1);
                shi += __shfl_xor_sync(0xffffffffu, shi, 2);
                if (c == 0) {
                    atomicAdd(&sAcc[mg * 64 + mt * 16 + r], slo);
                    atomicAdd(&sAcc[mg * 64 + mt * 16 + r + 8], shi);
                }
            }
        }
        __syncthreads();   // sAcc complete

        const int row0 = tile * TILE_R;
        if (tid < TILE_R) {
            int grow = row0 + tid;
            float Araw = sAcc[tid] + bw0;
            sAcc[tid] = 0.f;
            float e = 0.f;
            if (grow < N_ROWS) { e = __expf(Araw); g_E[grow] = e; esum += e; }
            sE[tid] = e;
        }
        __syncthreads();   // sE ready

        // ---- fused weighted-bag reduction (half2 per thread, d = 2*tid, 2*tid+1)
        if (tid < 64) {
            float w0 = 0.f, w1 = 0.f;
            const char* st = stage + tid * 4;
            #pragma unroll 8
            for (int rr = 0; rr < TILE_R; rr++) {
                __half2 hv = *(const __half2*)(st + rr * ST_ROW_B);
                float2 f = __half22float2(hv);
                float e = sE[rr];
                w0 = fmaf(e, f.x, w0);
                w1 = fmaf(e, f.y, w1);
            }
            ws0 += w0; ws1 += w1;
        }

        // ---- load next tile into the other stage buffer (no sync needed:
        // stage[1-parity] readers all finished before this iteration's top sync)
        int nxt = tile + GRID_SCORES;
        if (nxt < NTILES)
            load_tile_f16(smem + (parity ? OFF_ST0 : OFF_ST1), bag, nxt, tid);

        parity ^= 1;
    }

    // ---- final reductions
    if (tid < 64) {
        atomicAdd(&g_wsum[2 * tid], ws0);
        atomicAdd(&g_wsum[2 * tid + 1], ws1);
    }
    float s = esum;
    #pragma unroll
    for (int o = 16; o; o >>= 1) s += __shfl_xor_sync(0xffffffffu, s, o);
    if (lane == 0 && s != 0.f) atomicAdd(&g_sumexp, s);
}

__global__ void k_alpha(float* __restrict__ out, const float* __restrict__ b2) {
    int i = blockIdx.x * blockDim.x + threadIdx.x;
    if (i == 0) out[0] = b2[0];
    float invS = __frcp_rn(g_sumexp);
    int j0 = i * 2;
    #pragma unroll
    for (int k = 0; k < 2; k++) {
        int j = j0 + k;
        if (j < N_ROWS) out[1 + j] = g_E[j] * invS;
    }
}

// parallel head: 8 blocks x 8 warps, warp handles 4 outputs; atomicAdd partials
__global__ void k_head(const float* __restrict__ gf,
                       const float* __restrict__ W1, const float* __restrict__ b1,
                       const float* __restrict__ W2, float* __restrict__ out) {
    __shared__ float fused[D + GDIM];
    const int tid = threadIdx.x, lane = tid & 31, wid = tid >> 5;
    const float invS = __frcp_rn(g_sumexp);
    if (tid < D) fused[tid] = g_wsum[tid] * invS;
    else if (tid < D + GDIM) fused[tid] = gf[tid - D];
    __syncthreads();

    float part = 0.f;
    #pragma unroll
    for (int q = 0; q < 4; q++) {
        int m = blockIdx.x * 32 + wid * 4 + q;
        float s = 0.f;
        #pragma unroll
        for (int t = 0; t < 6; t++)
            s = fmaf(W1[m * (D + GDIM) + t * 32 + lane], fused[t * 32 + lane], s);
        #pragma unroll
        for (int o = 16; o; o >>= 1) s += __shfl_xor_sync(0xffffffffu, s, o);
        if (lane == 0) {
            float h = s + b1[m];
            h = h > 0.f ? h : 0.01f * h;
            part = fmaf(h, W2[m], part);
        }
    }
    if (lane == 0) atomicAdd(out, part);
}

extern "C" void kernel_launch(void* const* d_in, const int* in_sizes, int n_in,
                              void* d_out, int out_size)
{
    const float* bag = (const float*)d_in[0];
    const float* gf  = (const float*)d_in[1];
    const float* Wv  = (const float*)d_in[2];
    const float* bv  = (const float*)d_in[3];
    const float* Wu  = (const float*)d_in[4];
    const float* bu  = (const float*)d_in[5];
    const float* Ww  = (const float*)d_in[6];
    const float* bw  = (const float*)d_in[7];
    const float* W1  = (const float*)d_in[8];
    const float* b1  = (const float*)d_in[9];
    const float* W2  = (const float*)d_in[10];
    const float* b2  = (const float*)d_in[11];
    float* out = (float*)d_out;

    cudaFuncSetAttribute(k_scores, cudaFuncAttributeMaxDynamicSharedMemorySize, SMEM_TOTAL);

    k_init<<<1, 256>>>();
    k_scores<<<GRID_SCORES, 256, SMEM_TOTAL>>>(bag, Wv, bv, Wu, bu, Ww, bw);
    k_alpha<<<(N_ROWS + 511) / 512, 256>>>(out, b2);
    k_head<<<8, 256>>>(gf, W1, b1, W2, out);
}

// round 8
// speedup vs baseline: 2.4724x; 1.4101x over previous
#include <cuda_runtime.h>
#include <cuda_fp16.h>
#include <math.h>
#include <stdint.h>

#define N_ROWS 500000
#define D 128
#define H 128
#define GDIM 64
#define M 256
#define TILE_R 64
#define NTILES ((N_ROWS + TILE_R - 1) / TILE_R)   // 7813
#define GRID_SCORES 296                           // 2 CTAs / SM

// fp16 staging: row = 128 halves + 8 pad = 272 B -> (4r+c) banks, conflict-free frags
#define ST_ROW_B 272
#define ST_BUF_B (TILE_R * ST_ROW_B)     // 17408
#define OFF_ST0 0
#define OFF_ST1 ST_BUF_B                 // 17408
// B16 unpadded: [mat2][ks8][n128][32B]
#define B_MAT_B (8 * 128 * 32)           // 32768
#define OFF_B16 (2 * ST_BUF_B)           // 34816
#define OFF_SE   (OFF_B16 + 2 * B_MAT_B) // 100352
#define OFF_SACC (OFF_SE + 256)          // 100608
#define SMEM_TOTAL (OFF_SACC + 256)      // 100864  (x2 CTAs = 201728 <= 228KB)

// -------- scratch --------
__device__ float g_E[N_ROWS];
__device__ float g_sumexp;
__device__ float g_wsum[D];

__device__ __forceinline__ void mma_f16_k16(float d[4], const uint32_t a[4], uint32_t b0, uint32_t b1) {
    asm volatile(
        "mma.sync.aligned.m16n8k16.row.col.f32.f16.f16.f32 "
        "{%0,%1,%2,%3}, {%4,%5,%6,%7}, {%8,%9}, {%0,%1,%2,%3};"
        : "+f"(d[0]), "+f"(d[1]), "+f"(d[2]), "+f"(d[3])
        : "r"(a[0]), "r"(a[1]), "r"(a[2]), "r"(a[3]), "r"(b0), "r"(b1));
}
__device__ __forceinline__ float tanh_fast(float x) {
    float r;
    asm("tanh.approx.f32 %0, %1;" : "=f"(r) : "f"(x));
    return r;
}
__device__ __forceinline__ uint32_t pack_h2(float lo, float hi) {
    __half2 h = __floats2half2_rn(lo, hi);
    return *(uint32_t*)&h;
}

__global__ void k_init() {
    int t = threadIdx.x;
    if (t < D) g_wsum[t] = 0.f;
    if (t == 0) g_sumexp = 0.f;
}

// load one 64-row tile: gmem fp32 -> cvt fp16 -> smem stage
__device__ __forceinline__ void load_tile_f16(char* stage, const float* __restrict__ bag,
                                              int tile, int tid) {
    const int row0 = tile * TILE_R;
    #pragma unroll
    for (int i = 0; i < 8; i++) {
        int chunk = tid + i * 256;          // 0..2047
        int row = chunk >> 5, c4 = chunk & 31;
        int grow = row0 + row;
        float4 v = make_float4(0.f, 0.f, 0.f, 0.f);
        if (grow < N_ROWS) v = ((const float4*)bag)[grow * 32 + c4];
        uint2 pk = make_uint2(pack_h2(v.x, v.y), pack_h2(v.z, v.w));
        *(uint2*)(stage + row * ST_ROW_B + c4 * 8) = pk;
    }
}

// ---------------------------------------------------------------------------
// Persistent, 2 CTAs/SM: fp16 m16n8k16 GEMMs (V,U), fp32 accum, gated epilogue,
// fused exp + weighted-bag reduction. 64-row tiles.
// ---------------------------------------------------------------------------
__global__ void __launch_bounds__(256, 2)
k_scores(const float* __restrict__ bag,
         const float* __restrict__ Wv, const float* __restrict__ bv,
         const float* __restrict__ Wu, const float* __restrict__ bu,
         const float* __restrict__ Ww, const float* __restrict__ bwp)
{
    extern __shared__ __align__(128) char smem[];
    const int tid = threadIdx.x, lane = tid & 31, wid = tid >> 5;
    float* sE   = (float*)(smem + OFF_SE);
    float* sAcc = (float*)(smem + OFF_SACC);

    // ---- repack weights -> fp16 [mat][ks8][n][32B = 16 halves]
    for (int idx = tid; idx < 2 * 128 * 8; idx += 256) {
        int mat = idx >> 10, n = (idx >> 3) & 127, ks = idx & 7;
        const float* wr = (mat ? Wu : Wv) + n * 128 + ks * 16;
        float4 f0 = *(const float4*)(wr);
        float4 f1 = *(const float4*)(wr + 4);
        float4 f2 = *(const float4*)(wr + 8);
        float4 f3 = *(const float4*)(wr + 12);
        char* dst = smem + OFF_B16 + mat * B_MAT_B + ks * 4096 + n * 32;
        *(uint4*)(dst)      = make_uint4(pack_h2(f0.x, f0.y), pack_h2(f0.z, f0.w),
                                         pack_h2(f1.x, f1.y), pack_h2(f1.z, f1.w));
        *(uint4*)(dst + 16) = make_uint4(pack_h2(f2.x, f2.y), pack_h2(f2.z, f2.w),
                                         pack_h2(f3.x, f3.y), pack_h2(f3.z, f3.w));
    }
    if (tid < TILE_R) sAcc[tid] = 0.f;

    // ---- per-thread epilogue params (h = wid*16 + nt*8 + c*2 + jj)
    const int r = lane >> 2, c = lane & 3;
    float ww_[2][2], bv_[2][2], bu_[2][2];
    #pragma unroll
    for (int nt = 0; nt < 2; nt++)
        #pragma unroll
        for (int jj = 0; jj < 2; jj++) {
            int h = wid * 16 + nt * 8 + c * 2 + jj;
            ww_[nt][jj] = Ww[h]; bv_[nt][jj] = bv[h]; bu_[nt][jj] = bu[h];
        }
    const float bw0 = bwp[0];

    // prologue: first tile into stage0
    load_tile_f16(smem + OFF_ST0, bag, blockIdx.x, tid);

    float esum = 0.f, ws0 = 0.f, ws1 = 0.f;

    int parity = 0;
    for (int tile = blockIdx.x; tile < NTILES; tile += GRID_SCORES) {
        __syncthreads();   // stage[parity] written; sAcc zeroed; B16 ready (1st iter)
        char* stage = smem + (parity ? OFF_ST1 : OFF_ST0);

        float accV[4][2][4], accU[4][2][4];
        #pragma unroll
        for (int mt = 0; mt < 4; mt++)
            #pragma unroll
            for (int nt = 0; nt < 2; nt++)
                #pragma unroll
                for (int q = 0; q < 4; q++) { accV[mt][nt][q] = 0.f; accU[mt][nt][q] = 0.f; }

        const char* aB = stage + r * ST_ROW_B + c * 4;
        const char* bB = smem + OFF_B16 + (wid * 16 + r) * 32 + c * 4;

        #pragma unroll
        for (int ks = 0; ks < 8; ks++) {
            uint32_t a[4][4];
            #pragma unroll
            for (int mt = 0; mt < 4; mt++) {
                const char* ap = aB + mt * 16 * ST_ROW_B + ks * 32;
                a[mt][0] = *(const uint32_t*)(ap);
                a[mt][1] = *(const uint32_t*)(ap + 8 * ST_ROW_B);
                a[mt][2] = *(const uint32_t*)(ap + 16);
                a[mt][3] = *(const uint32_t*)(ap + 8 * ST_ROW_B + 16);
            }
            const char* bk = bB + ks * 4096;
            uint32_t bV0[2], bV1[2], bU0[2], bU1[2];
            #pragma unroll
            for (int nt = 0; nt < 2; nt++) {
                const char* bn = bk + nt * 8 * 32;
                bV0[nt] = *(const uint32_t*)(bn);
                bV1[nt] = *(const uint32_t*)(bn + 16);
                bU0[nt] = *(const uint32_t*)(bn + B_MAT_B);
                bU1[nt] = *(const uint32_t*)(bn + B_MAT_B + 16);
            }
            #pragma unroll
            for (int mt = 0; mt < 4; mt++) {
                mma_f16_k16(accV[mt][0], a[mt], bV0[0], bV1[0]);
                mma_f16_k16(accV[mt][1], a[mt], bV0[1], bV1[1]);
                mma_f16_k16(accU[mt][0], a[mt], bU0[0], bU1[0]);
                mma_f16_k16(accU[mt][1], a[mt], bU0[1], bU1[1]);
            }
        }

        // ---- epilogue: gate + Ww partial dot
        #pragma unroll
        for (int mt = 0; mt < 4; mt++) {
            float slo = 0.f, shi = 0.f;
            #pragma unroll
            for (int nt = 0; nt < 2; nt++)
                #pragma unroll
                for (int jj = 0; jj < 2; jj++) {
                    float v = accV[mt][nt][jj] + bv_[nt][jj];
                    float u = accU[mt][nt][jj] + bu_[nt][jj];
                    float sg = fmaf(0.5f, tanh_fast(0.5f * u), 0.5f);
                    slo = fmaf(ww_[nt][jj] * tanh_fast(v), sg, slo);
                    v = accV[mt][nt][2 + jj] + bv_[nt][jj];
                    u = accU[mt][nt][2 + jj] + bu_[nt][jj];
                    sg = fmaf(0.5f, tanh_fast(0.5f * u), 0.5f);
                    shi = fmaf(ww_[nt][jj] * tanh_fast(v), sg, shi);
                }
            slo += __shfl_xor_sync(0xffffffffu, slo, 1);
            slo += __shfl_xor_sync(0xffffffffu, slo, 2);
            shi += __shfl_xor_sync(0xffffffffu, shi, 1);
            shi += __shfl_xor_sync(0xffffffffu, shi, 2);
            if (c == 0) {
                atomicAdd(&sAcc[mt * 16 + r], slo);
                atomicAdd(&sAcc[mt * 16 + r + 8], shi);
            }
        }
        __syncthreads();   // sAcc complete

        const int row0 = tile * TILE_R;
        if (tid < TILE_R) {
            int grow = row0 + tid;
            float Araw = sAcc[tid] + bw0;
            sAcc[tid] = 0.f;
            float e = 0.f;
            if (grow < N_ROWS) { e = __expf(Araw); g_E[grow] = e; esum += e; }
            sE[tid] = e;
        }
        __syncthreads();   // sE ready

        // ---- fused weighted-bag reduction (half2 per thread, d = 2*tid, 2*tid+1)
        if (tid < 64) {
            float w0 = 0.f, w1 = 0.f;
            const char* st = stage + tid * 4;
            #pragma unroll 8
            for (int rr = 0; rr < TILE_R; rr++) {
                __half2 hv = *(const __half2*)(st + rr * ST_ROW_B);
                float2 f = __half22float2(hv);
                float e = sE[rr];
                w0 = fmaf(e, f.x, w0);
                w1 = fmaf(e, f.y, w1);
            }
            ws0 += w0; ws1 += w1;
        }

        // ---- prefetch next tile into the other stage buffer
        int nxt = tile + GRID_SCORES;
        if (nxt < NTILES)
            load_tile_f16(smem + (parity ? OFF_ST0 : OFF_ST1), bag, nxt, tid);

        parity ^= 1;
    }

    // ---- final reductions
    if (tid < 64) {
        atomicAdd(&g_wsum[2 * tid], ws0);
        atomicAdd(&g_wsum[2 * tid + 1], ws1);
    }
    float s = esum;
    #pragma unroll
    for (int o = 16; o; o >>= 1) s += __shfl_xor_sync(0xffffffffu, s, o);
    if (lane == 0 && s != 0.f) atomicAdd(&g_sumexp, s);
}

__global__ void k_alpha(float* __restrict__ out, const float* __restrict__ b2) {
    int i = blockIdx.x * blockDim.x + threadIdx.x;
    if (i == 0) out[0] = b2[0];
    float invS = __frcp_rn(g_sumexp);
    int j0 = i * 2;
    #pragma unroll
    for (int k = 0; k < 2; k++) {
        int j = j0 + k;
        if (j < N_ROWS) out[1 + j] = g_E[j] * invS;
    }
}

// parallel head: 8 blocks x 8 warps, warp handles 4 outputs; atomicAdd partials
__global__ void k_head(const float* __restrict__ gf,
                       const float* __restrict__ W1, const float* __restrict__ b1,
                       const float* __restrict__ W2, float* __restrict__ out) {
    __shared__ float fused[D + GDIM];
    const int tid = threadIdx.x, lane = tid & 31, wid = tid >> 5;
    const float invS = __frcp_rn(g_sumexp);
    if (tid < D) fused[tid] = g_wsum[tid] * invS;
    else if (tid < D + GDIM) fused[tid] = gf[tid - D];
    __syncthreads();

    float part = 0.f;
    #pragma unroll
    for (int q = 0; q < 4; q++) {
        int m = blockIdx.x * 32 + wid * 4 + q;
        float s = 0.f;
        #pragma unroll
        for (int t = 0; t < 6; t++)
            s = fmaf(W1[m * (D + GDIM) + t * 32 + lane], fused[t * 32 + lane], s);
        #pragma unroll
        for (int o = 16; o; o >>= 1) s += __shfl_xor_sync(0xffffffffu, s, o);
        if (lane == 0) {
            float h = s + b1[m];
            h = h > 0.f ? h : 0.01f * h;
            part = fmaf(h, W2[m], part);
        }
    }
    if (lane == 0) atomicAdd(out, part);
}

extern "C" void kernel_launch(void* const* d_in, const int* in_sizes, int n_in,
                              void* d_out, int out_size)
{
    const float* bag = (const float*)d_in[0];
    const float* gf  = (const float*)d_in[1];
    const float* Wv  = (const float*)d_in[2];
    const float* bv  = (const float*)d_in[3];
    const float* Wu  = (const float*)d_in[4];
    const float* bu  = (const float*)d_in[5];
    const float* Ww  = (const float*)d_in[6];
    const float* bw  = (const float*)d_in[7];
    const float* W1  = (const float*)d_in[8];
    const float* b1  = (const float*)d_in[9];
    const float* W2  = (const float*)d_in[10];
    const float* b2  = (const float*)d_in[11];
    float* out = (float*)d_out;

    cudaFuncSetAttribute(k_scores, cudaFuncAttributeMaxDynamicSharedMemorySize, SMEM_TOTAL);

    k_init<<<1, 256>>>();
    k_scores<<<GRID_SCORES, 256, SMEM_TOTAL>>>(bag, Wv, bv, Wu, bu, Ww, bw);
    k_alpha<<<(N_ROWS + 511) / 512, 256>>>(out, b2);
    k_head<<<8, 256>>>(gf, W1, b1, W2, out);
}